// round 10
// baseline (speedup 1.0000x reference)
#include <cuda_runtime.h>
#include <cstdint>

// Paged GQA decode attention, split-KV, single fused kernel.
// R10: occupancy push — Q in smem (volatile LDS), DEPTH=4, smem overlay,
// __launch_bounds__(128,6) => 6 CTAs/SM (24 warps) instead of 4.
#define BB    64
#define HQ    32
#define HKV   8
#define GG    4        // HQ / HKV
#define DD    128
#define SS    16       // page size
#define MBMB  128      // max blocks per seq
#define MAXL  (SS*MBMB)   // 2048
#define CHUNK 256
#define NCHUNK (MAXL/CHUNK)  // 8
#define NW    4        // warps per CTA
#define DEPTH 4        // cp.async ring stages per warp
#define SCALE 0.08838834764831845f

__device__ float g_part_acc[(size_t)BB*HKV*NCHUNK*GG*DD];   // 8 MB
__device__ float g_part_l[BB*HKV*NCHUNK*GG];
__device__ int   g_ctr[BB*HKV];          // zero-init; each replay returns it to 0

__device__ __forceinline__ void cpa16(uint32_t saddr, const void* gaddr) {
    asm volatile("cp.async.cg.shared.global [%0], [%1], 16;"
                 :: "r"(saddr), "l"(gaddr));
}
__device__ __forceinline__ void cpa_commit() {
    asm volatile("cp.async.commit_group;");
}
__device__ __forceinline__ void cpa_wait2() {
    asm volatile("cp.async.wait_group 2;");   // DEPTH-2
}
__device__ __forceinline__ void cpa_wait0() {
    asm volatile("cp.async.wait_group 0;");
}
// volatile smem v4 load: keeps Q out of registers (no hoist/CSE)
__device__ __forceinline__ float4 lds4v(uint32_t addr) {
    float4 r;
    asm volatile("ld.shared.v4.f32 {%0,%1,%2,%3}, [%4];"
                 : "=f"(r.x), "=f"(r.y), "=f"(r.z), "=f"(r.w) : "r"(addr));
    return r;
}

__global__ __launch_bounds__(NW*32, 6) void attn_pass1(
    const float* __restrict__ q,
    const float* __restrict__ kc,
    const float* __restrict__ vc,
    const int*   __restrict__ btab,
    const int*   __restrict__ clen,
    float*       __restrict__ out)
{
    const int chunk = blockIdx.x;
    const int kvh   = blockIdx.y;
    const int b     = blockIdx.z;
    const int L     = clen[b];
    const int start = chunk * CHUNK;

    const int tid  = threadIdx.x;
    const int w    = tid >> 5;
    const int lane = tid & 31;
    const int h    = lane >> 4;    // half-warp: which token of the pair
    const int sl   = lane & 15;    // sub-lane: owns d-quads sl and 16+sl

    // Per-warp cp.async ring: [warp][stage][4 slots (K0,K1,V0,V1)][32 lanes]
    __shared__ float4 ring[NW][DEPTH][4][32];          // 32 KB
    __shared__ float4 s_q[2][GG][16];                  // 2 KB, scaled Q
    __shared__ int    s_bt[CHUNK/SS];
    __shared__ int    s_last;

    if (start < L) {
        const int n = min(L - start, CHUNK);   // tokens in this chunk

        if (tid < CHUNK/SS) s_bt[tid] = btab[b*MBMB + (start>>4) + tid];
        // stage scaled Q once: thread t holds head g=t>>5, quad qd=t&31
        {
            const int g  = tid >> 5;
            const int qd = tid & 31;
            const float4* q4 = (const float4*)(q + ((size_t)b*HQ + (size_t)kvh*GG)*DD);
            float4 t = q4[(size_t)g*(DD/4) + qd];
            s_q[qd>>4][g][qd&15] =
                make_float4(t.x*SCALE, t.y*SCALE, t.z*SCALE, t.w*SCALE);
        }
        __syncthreads();

        const uint32_t qbase =
            (uint32_t)__cvta_generic_to_shared(&s_q[0][0][0]) + (uint32_t)sl*16u;

        float  l[GG];
        float4 a0[GG], a1[GG];
        #pragma unroll
        for (int g = 0; g < GG; g++) {
            l[g] = 0.f;
            a0[g] = make_float4(0.f,0.f,0.f,0.f);
            a1[g] = make_float4(0.f,0.f,0.f,0.f);
        }

        const float4* k4 = (const float4*)kc;
        const float4* v4 = (const float4*)vc;

        // iteration it handles tokens 2*(w + it*NW) + {0,1}
        const int half  = (n + 1) >> 1;
        const int itEnd = (half > w) ? (half - w + NW - 1)/NW : 0;

        const uint32_t ringbase =
            (uint32_t)__cvta_generic_to_shared(&ring[w][0][0][0]) + (uint32_t)lane*16u;

        auto issue = [&](int it) {
            if (it < itEnd) {
                const int tok = 2*(w + it*NW) + h;
                const size_t rb =
                    ((size_t)(s_bt[tok>>4]*SS + (tok & 15))*HKV + kvh)*(DD/4);
                const uint32_t sb = ringbase + (uint32_t)(it % DEPTH)*(4u*512u);
                cpa16(sb + 0*512u, k4 + rb + sl);
                cpa16(sb + 1*512u, k4 + rb + 16 + sl);
                cpa16(sb + 2*512u, v4 + rb + sl);
                cpa16(sb + 3*512u, v4 + rb + 16 + sl);
            }
            cpa_commit();
        };

        #pragma unroll
        for (int p = 0; p < DEPTH-1; p++) issue(p);

        for (int it = 0; it < itEnd; it++) {
            cpa_wait2();                       // stage it%DEPTH has arrived
            issue(it + DEPTH - 1);

            const int st = it % DEPTH;
            float4 kc0 = ring[w][st][0][lane];
            float4 kc1 = ring[w][st][1][lane];
            float4 vc0 = ring[w][st][2][lane];
            float4 vc1 = ring[w][st][3][lane];

            const int tok  = 2*(w + it*NW) + h;
            const float bias = (tok < n) ? 0.f : -1e30f;

            float s[GG];
            #pragma unroll
            for (int g = 0; g < GG; g++) {
                float4 qa = lds4v(qbase + (uint32_t)g*256u);
                float4 qb = lds4v(qbase + (uint32_t)g*256u + 1024u);
                s[g] = kc0.x*qa.x + kc0.y*qa.y + kc0.z*qa.z + kc0.w*qa.w
                     + kc1.x*qb.x + kc1.y*qb.y + kc1.z*qb.z + kc1.w*qb.w;
            }

            #pragma unroll
            for (int off = 8; off; off >>= 1) {
                #pragma unroll
                for (int g = 0; g < GG; g++)
                    s[g] += __shfl_xor_sync(0xffffffffu, s[g], off);
            }

            #pragma unroll
            for (int g = 0; g < GG; g++) {
                float p = __expf(s[g] + bias);
                l[g] += p;
                a0[g].x += p*vc0.x; a0[g].y += p*vc0.y; a0[g].z += p*vc0.z; a0[g].w += p*vc0.w;
                a1[g].x += p*vc1.x; a1[g].y += p*vc1.y; a1[g].z += p*vc1.z; a1[g].w += p*vc1.w;
            }
        }
        cpa_wait0();   // drain tail groups: this warp's ring region is now dead

        // merge the two halves (same d-quads, disjoint token subsets)
        #pragma unroll
        for (int g = 0; g < GG; g++) {
            a0[g].x += __shfl_xor_sync(0xffffffffu, a0[g].x, 16);
            a0[g].y += __shfl_xor_sync(0xffffffffu, a0[g].y, 16);
            a0[g].z += __shfl_xor_sync(0xffffffffu, a0[g].z, 16);
            a0[g].w += __shfl_xor_sync(0xffffffffu, a0[g].w, 16);
            a1[g].x += __shfl_xor_sync(0xffffffffu, a1[g].x, 16);
            a1[g].y += __shfl_xor_sync(0xffffffffu, a1[g].y, 16);
            a1[g].z += __shfl_xor_sync(0xffffffffu, a1[g].z, 16);
            a1[g].w += __shfl_xor_sync(0xffffffffu, a1[g].w, 16);
            l[g]   += __shfl_xor_sync(0xffffffffu, l[g],   16);
        }

        // per-warp merge buffers OVERLAY the warp's own (dead) ring region:
        //   stage 0 (2 KB): float4 [GG][32] accumulators
        //   stage 1 start : float  [GG]     l sums
        float4* myA = reinterpret_cast<float4*>(&ring[w][0][0][0]);
        float*  myL = reinterpret_cast<float*> (&ring[w][1][0][0]);
        if (h == 0) {
            #pragma unroll
            for (int g = 0; g < GG; g++) {
                myA[g*32 + sl]      = a0[g];
                myA[g*32 + 16 + sl] = a1[g];
                if (sl == 0) myL[g] = l[g];
            }
        }
        __syncthreads();

        {
            const int g = w;  // warp index now indexes head g
            float4 t = make_float4(0.f,0.f,0.f,0.f);
            float  Ls = 0.f;
            #pragma unroll
            for (int ww = 0; ww < NW; ww++) {
                const float4* wA = reinterpret_cast<const float4*>(&ring[ww][0][0][0]);
                const float*  wL = reinterpret_cast<const float*> (&ring[ww][1][0][0]);
                float4 u = wA[g*32 + lane];
                t.x += u.x; t.y += u.y; t.z += u.z; t.w += u.w;
                Ls += wL[g];
            }
            const size_t sidx = (((size_t)(b*HKV + kvh)*NCHUNK + chunk)*GG + g);
            ((float4*)g_part_acc)[sidx*(DD/4) + lane] = t;
            if (lane == 0) g_part_l[sidx] = Ls;
        }
        __syncthreads();
    }

    // ---- arrival: every CTA of this (b,kvh), including empty chunks ----
    if (tid == 0) {
        __threadfence();                       // partials visible before arrival
        int old = atomicAdd(&g_ctr[b*HKV + kvh], 1);
        s_last = (old == NCHUNK - 1);
    }
    __syncthreads();

    if (s_last) {
        if (tid == 0) g_ctr[b*HKV + kvh] = 0;  // reset for next graph replay
        __threadfence();                       // acquire side

        // combine <= NCHUNK chunk partials: warp w = head g, lane = d-quad
        const int g   = w;
        const int nch = (L + CHUNK - 1) / CHUNK;
        const size_t base = ((size_t)(b*HKV + kvh)*NCHUNK)*GG + g;

        float Ls = 0.f;
        float4 a = make_float4(0.f, 0.f, 0.f, 0.f);
        #pragma unroll
        for (int c = 0; c < NCHUNK; c++) {     // predicated: MLP = 8
            if (c < nch) {
                const size_t sidx = base + (size_t)c*GG;
                Ls += g_part_l[sidx];
                float4 av = ((const float4*)g_part_acc)[sidx*(DD/4) + lane];
                a.x += av.x; a.y += av.y; a.z += av.z; a.w += av.w;
            }
        }
        const float inv = 1.0f / Ls;
        const int qh = kvh*GG + g;
        ((float4*)out)[((size_t)b*HQ + qh)*(DD/4) + lane] =
            make_float4(a.x*inv, a.y*inv, a.z*inv, a.w*inv);
    }
}

extern "C" void kernel_launch(void* const* d_in, const int* in_sizes, int n_in,
                              void* d_out, int out_size)
{
    const float* q    = (const float*)d_in[0];
    const float* kc   = (const float*)d_in[1];
    const float* vc   = (const float*)d_in[2];
    const int*   btab = (const int*)d_in[3];
    const int*   clen = (const int*)d_in[4];
    float*       out  = (float*)d_out;

    dim3 grid1(NCHUNK, HKV, BB);
    attn_pass1<<<grid1, NW*32>>>(q, kc, vc, btab, clen, out);
}

// round 11
// speedup vs baseline: 1.0852x; 1.0852x over previous
#include <cuda_runtime.h>
#include <cstdint>

// Paged GQA decode attention, split-KV, single fused kernel.
// R11: revert to R9 core (Q in regs, per-warp cp.async ring DEPTH=5),
// CHUNK 256->128 to halve the straggler tail.
#define BB    64
#define HQ    32
#define HKV   8
#define GG    4        // HQ / HKV
#define DD    128
#define SS    16       // page size
#define MBMB  128      // max blocks per seq
#define MAXL  (SS*MBMB)   // 2048
#define CHUNK 128
#define NCHUNK (MAXL/CHUNK)  // 16
#define NW    4        // warps per CTA
#define DEPTH 5        // cp.async ring stages per warp
#define SCALE 0.08838834764831845f

// Split-KV partial scratch + arrival counters (allocation-free __device__ globals).
__device__ float g_part_acc[(size_t)BB*HKV*NCHUNK*GG*DD];   // 16 MB
__device__ float g_part_l[BB*HKV*NCHUNK*GG];
__device__ int   g_ctr[BB*HKV];          // zero-init; each replay returns it to 0

__device__ __forceinline__ float dot4(float4 a, float4 b) {
    return a.x*b.x + a.y*b.y + a.z*b.z + a.w*b.w;
}

__device__ __forceinline__ void cpa16(uint32_t saddr, const void* gaddr) {
    asm volatile("cp.async.cg.shared.global [%0], [%1], 16;"
                 :: "r"(saddr), "l"(gaddr));
}
__device__ __forceinline__ void cpa_commit() {
    asm volatile("cp.async.commit_group;");
}
__device__ __forceinline__ void cpa_wait3() {
    asm volatile("cp.async.wait_group 3;");   // DEPTH-2
}
__device__ __forceinline__ void cpa_wait0() {
    asm volatile("cp.async.wait_group 0;");
}

__global__ __launch_bounds__(NW*32) void attn_pass1(
    const float* __restrict__ q,
    const float* __restrict__ kc,
    const float* __restrict__ vc,
    const int*   __restrict__ btab,
    const int*   __restrict__ clen,
    float*       __restrict__ out)
{
    const int chunk = blockIdx.x;
    const int kvh   = blockIdx.y;
    const int b     = blockIdx.z;
    const int L     = clen[b];
    const int start = chunk * CHUNK;

    const int tid  = threadIdx.x;
    const int w    = tid >> 5;
    const int lane = tid & 31;
    const int h    = lane >> 4;    // half-warp: which token of the pair
    const int sl   = lane & 15;    // sub-lane: owns d-quads sl and 16+sl

    __shared__ float4 ring[NW][DEPTH][4][32];          // 40 KB
    __shared__ int    s_bt[CHUNK/SS];
    __shared__ float4 smA[NW][GG][32];                 // 2 KB
    __shared__ float  smL[NW][GG];
    __shared__ int    s_last;

    if (start < L) {
        const int n = min(L - start, CHUNK);   // tokens in this chunk

        if (tid < CHUNK/SS) s_bt[tid] = btab[b*MBMB + (start>>4) + tid];
        __syncthreads();

        // Q: lane owns d-quads sl and 16+sl for each of the 4 grouped heads.
        float4 q0[GG], q1[GG];
        {
            const float4* q4 = (const float4*)(q + ((size_t)b*HQ + (size_t)kvh*GG)*DD);
            #pragma unroll
            for (int g = 0; g < GG; g++) {
                float4 t = q4[g*(DD/4) + sl];
                q0[g] = make_float4(t.x*SCALE, t.y*SCALE, t.z*SCALE, t.w*SCALE);
                t = q4[g*(DD/4) + 16 + sl];
                q1[g] = make_float4(t.x*SCALE, t.y*SCALE, t.z*SCALE, t.w*SCALE);
            }
        }

        float  l[GG];
        float4 a0[GG], a1[GG];
        #pragma unroll
        for (int g = 0; g < GG; g++) {
            l[g] = 0.f;
            a0[g] = make_float4(0.f,0.f,0.f,0.f);
            a1[g] = make_float4(0.f,0.f,0.f,0.f);
        }

        const float4* k4 = (const float4*)kc;
        const float4* v4 = (const float4*)vc;

        // iteration it handles tokens 2*(w + it*NW) + {0,1}
        const int half  = (n + 1) >> 1;
        const int itEnd = (half > w) ? (half - w + NW - 1)/NW : 0;

        const uint32_t ringbase =
            (uint32_t)__cvta_generic_to_shared(&ring[w][0][0][0]) + (uint32_t)lane*16u;

        auto issue = [&](int it) {
            if (it < itEnd) {
                const int tok = 2*(w + it*NW) + h;
                const size_t rb =
                    ((size_t)(s_bt[tok>>4]*SS + (tok & 15))*HKV + kvh)*(DD/4);
                const uint32_t sb = ringbase + (uint32_t)(it % DEPTH)*(4u*512u);
                cpa16(sb + 0*512u, k4 + rb + sl);
                cpa16(sb + 1*512u, k4 + rb + 16 + sl);
                cpa16(sb + 2*512u, v4 + rb + sl);
                cpa16(sb + 3*512u, v4 + rb + 16 + sl);
            }
            cpa_commit();
        };

        #pragma unroll
        for (int p = 0; p < DEPTH-1; p++) issue(p);

        for (int it = 0; it < itEnd; it++) {
            cpa_wait3();                       // stage it%DEPTH has arrived
            issue(it + DEPTH - 1);

            const int st = it % DEPTH;
            float4 kc0 = ring[w][st][0][lane];
            float4 kc1 = ring[w][st][1][lane];
            float4 vc0 = ring[w][st][2][lane];
            float4 vc1 = ring[w][st][3][lane];

            const int tok  = 2*(w + it*NW) + h;
            const float bias = (tok < n) ? 0.f : -1e30f;

            float s[GG];
            #pragma unroll
            for (int g = 0; g < GG; g++)
                s[g] = dot4(kc0, q0[g]) + dot4(kc1, q1[g]);

            #pragma unroll
            for (int off = 8; off; off >>= 1) {
                #pragma unroll
                for (int g = 0; g < GG; g++)
                    s[g] += __shfl_xor_sync(0xffffffffu, s[g], off);
            }

            #pragma unroll
            for (int g = 0; g < GG; g++) {
                float p = __expf(s[g] + bias);
                l[g] += p;
                a0[g].x += p*vc0.x; a0[g].y += p*vc0.y; a0[g].z += p*vc0.z; a0[g].w += p*vc0.w;
                a1[g].x += p*vc1.x; a1[g].y += p*vc1.y; a1[g].z += p*vc1.z; a1[g].w += p*vc1.w;
            }
        }
        cpa_wait0();   // drain empty tail groups before smem reuse

        // merge the two halves (same d-quads, disjoint token subsets)
        #pragma unroll
        for (int g = 0; g < GG; g++) {
            a0[g].x += __shfl_xor_sync(0xffffffffu, a0[g].x, 16);
            a0[g].y += __shfl_xor_sync(0xffffffffu, a0[g].y, 16);
            a0[g].z += __shfl_xor_sync(0xffffffffu, a0[g].z, 16);
            a0[g].w += __shfl_xor_sync(0xffffffffu, a0[g].w, 16);
            a1[g].x += __shfl_xor_sync(0xffffffffu, a1[g].x, 16);
            a1[g].y += __shfl_xor_sync(0xffffffffu, a1[g].y, 16);
            a1[g].z += __shfl_xor_sync(0xffffffffu, a1[g].z, 16);
            a1[g].w += __shfl_xor_sync(0xffffffffu, a1[g].w, 16);
            l[g]   += __shfl_xor_sync(0xffffffffu, l[g],   16);
        }

        if (h == 0) {
            #pragma unroll
            for (int g = 0; g < GG; g++) {
                smA[w][g][sl]      = a0[g];
                smA[w][g][16 + sl] = a1[g];
                if (sl == 0) smL[w][g] = l[g];
            }
        }
        __syncthreads();

        {
            const int g = w;  // warp index now indexes head g
            float4 t = smA[0][g][lane];
            #pragma unroll
            for (int ww = 1; ww < NW; ww++) {
                float4 u = smA[ww][g][lane];
                t.x += u.x; t.y += u.y; t.z += u.z; t.w += u.w;
            }
            const size_t sidx = (((size_t)(b*HKV + kvh)*NCHUNK + chunk)*GG + g);
            ((float4*)g_part_acc)[sidx*(DD/4) + lane] = t;
            if (lane == 0)
                g_part_l[sidx] = smL[0][g] + smL[1][g] + smL[2][g] + smL[3][g];
        }
        __syncthreads();
    }

    // ---- arrival: every CTA of this (b,kvh), including empty chunks ----
    if (tid == 0) {
        __threadfence();                       // partials visible before arrival
        int old = atomicAdd(&g_ctr[b*HKV + kvh], 1);
        s_last = (old == NCHUNK - 1);
    }
    __syncthreads();

    if (s_last) {
        if (tid == 0) g_ctr[b*HKV + kvh] = 0;  // reset for next graph replay
        __threadfence();                       // acquire side

        // combine <= NCHUNK chunk partials: warp w = head g, lane = d-quad
        const int g   = w;
        const int nch = (L + CHUNK - 1) / CHUNK;
        const size_t base = ((size_t)(b*HKV + kvh)*NCHUNK)*GG + g;

        float Ls = 0.f;
        float4 a = make_float4(0.f, 0.f, 0.f, 0.f);
        #pragma unroll
        for (int c = 0; c < NCHUNK; c++) {     // predicated: MLP = 16
            if (c < nch) {
                const size_t sidx = base + (size_t)c*GG;
                Ls += g_part_l[sidx];
                float4 av = ((const float4*)g_part_acc)[sidx*(DD/4) + lane];
                a.x += av.x; a.y += av.y; a.z += av.z; a.w += av.w;
            }
        }
        const float inv = 1.0f / Ls;
        const int qh = kvh*GG + g;
        ((float4*)out)[((size_t)b*HQ + qh)*(DD/4) + lane] =
            make_float4(a.x*inv, a.y*inv, a.z*inv, a.w*inv);
    }
}

extern "C" void kernel_launch(void* const* d_in, const int* in_sizes, int n_in,
                              void* d_out, int out_size)
{
    const float* q    = (const float*)d_in[0];
    const float* kc   = (const float*)d_in[1];
    const float* vc   = (const float*)d_in[2];
    const int*   btab = (const int*)d_in[3];
    const int*   clen = (const int*)d_in[4];
    float*       out  = (float*)d_out;

    dim3 grid1(NCHUNK, HKV, BB);
    attn_pass1<<<grid1, NW*32>>>(q, kc, vc, btab, clen, out);
}